// round 12
// baseline (speedup 1.0000x reference)
#include <cuda_runtime.h>
#include <cstdint>
#include <math.h>

// ---------------- problem constants ----------------
#define NROWS 4096
#define DIM   1024
#define VOCAB 32000

// ---------------- tiling (fp8: 1 byte/elem) ----------------
#define BM 128
#define BN 256
#define BKB 128                    // K bytes (=elems) per stage; 128B rows = SW atom
#define NKITER (DIM / BKB)         // 8
#define NSTAGES 3
#define A_BYTES (BM * BKB)         // 16384
#define B_BYTES (BN * BKB)         // 32768
#define STAGE_BYTES (A_BYTES + B_BYTES)     // 49152
#define SMEM_BYTES (NSTAGES * STAGE_BYTES)  // 147456

// ---------------- device scratch (allocation-free rule) ----------------
__device__ uint8_t g_xb[(size_t)NROWS * DIM];   // 4 MB, e4m3 row-major
__device__ uint8_t g_Wb[(size_t)VOCAB * DIM];   // 32 MB, e4m3 row-major
__device__ float  g_rowS[NROWS];
__device__ float  g_tgt[NROWS];
__device__ double g_sumAll;
__device__ int    g_ymode;

// ---------------- PTX helpers ----------------
__device__ __forceinline__ uint32_t s2u(const void* p) {
    uint32_t a;
    asm("{ .reg .u64 t; cvta.to.shared.u64 t, %1; cvt.u32.u64 %0, t; }" : "=r"(a) : "l"(p));
    return a;
}

#define CP_ASYNC16(dst, src) \
    asm volatile("cp.async.cg.shared.global [%0], [%1], 16;" :: "r"(dst), "l"(src))
#define CP_COMMIT()  asm volatile("cp.async.commit_group;" ::: "memory")
#define CP_WAIT1()   asm volatile("cp.async.wait_group 1;"  ::: "memory")

__device__ __forceinline__ void ldsm4(uint32_t& r0, uint32_t& r1, uint32_t& r2, uint32_t& r3,
                                      uint32_t addr) {
    asm volatile("ldmatrix.sync.aligned.m8n8.x4.shared.b16 {%0,%1,%2,%3}, [%4];"
                 : "=r"(r0), "=r"(r1), "=r"(r2), "=r"(r3) : "r"(addr));
}

// fp8 e4m3 MMA, K=32, f32 accumulate.
// c0=(r,n) c1=(r,n+1) c2=(r+8,n) c3=(r+8,n+1)
__device__ __forceinline__ void mma16832q(float* c, const uint32_t* a, const uint32_t* b) {
    asm volatile(
        "mma.sync.aligned.m16n8k32.row.col.f32.e4m3.e4m3.f32 "
        "{%0,%1,%2,%3}, {%4,%5,%6,%7}, {%8,%9}, {%0,%1,%2,%3};"
        : "+f"(c[0]), "+f"(c[1]), "+f"(c[2]), "+f"(c[3])
        : "r"(a[0]), "r"(a[1]), "r"(a[2]), "r"(a[3]), "r"(b[0]), "r"(b[1]));
}

// pack 2 floats -> 2 e4m3 bytes (lo byte = first elem)
__device__ __forceinline__ uint16_t f2e4m3x2(float lo, float hi) {
    uint16_t d;
    asm("cvt.rn.satfinite.e4m3x2.f32 %0, %1, %2;" : "=h"(d) : "f"(hi), "f"(lo));
    return d;
}

// ---------------- init: zero accumulators + detect y dtype ----------------
__global__ void init_kernel(const void* yraw) {
    int t = blockIdx.x * blockDim.x + threadIdx.x;
    for (int j = t; j < NROWS; j += gridDim.x * blockDim.x) g_rowS[j] = 0.0f;
    if (blockIdx.x == 0) {
        __shared__ int bad;
        if (threadIdx.x == 0) { bad = 0; g_sumAll = 0.0; }
        __syncthreads();
        const long long* y64 = (const long long*)yraw;
        for (int j = threadIdx.x; j < 2048; j += blockDim.x) {
            long long v = y64[j];
            if (v < 0 || v >= VOCAB) bad = 1;
        }
        __syncthreads();
        if (threadIdx.x == 0) g_ymode = bad ? 0 : 1;
    }
}

// ---------------- convert fp32 -> e4m3 (row-major) ----------------
__global__ void convert_kernel(const float* __restrict__ x, const float* __restrict__ W) {
    long long i = (long long)blockIdx.x * blockDim.x + threadIdx.x;
    long long stride = (long long)gridDim.x * blockDim.x;
    const long long NX8 = (long long)NROWS * DIM / 8;    // 8 elems per thread-iter
    const long long NW8 = (long long)VOCAB * DIM / 8;
    for (long long j = i; j < NX8; j += stride) {
        const float4* s = (const float4*)(x + j * 8);
        float4 v0 = s[0], v1 = s[1];
        uint32_t lo = (uint32_t)f2e4m3x2(v0.x, v0.y) | ((uint32_t)f2e4m3x2(v0.z, v0.w) << 16);
        uint32_t hi = (uint32_t)f2e4m3x2(v1.x, v1.y) | ((uint32_t)f2e4m3x2(v1.z, v1.w) << 16);
        ((uint2*)g_xb)[j] = make_uint2(lo, hi);
    }
    for (long long j = i; j < NW8; j += stride) {
        const float4* s = (const float4*)(W + j * 8);
        float4 v0 = s[0], v1 = s[1];
        uint32_t lo = (uint32_t)f2e4m3x2(v0.x, v0.y) | ((uint32_t)f2e4m3x2(v0.z, v0.w) << 16);
        uint32_t hi = (uint32_t)f2e4m3x2(v1.x, v1.y) | ((uint32_t)f2e4m3x2(v1.z, v1.w) << 16);
        ((uint2*)g_Wb)[j] = make_uint2(lo, hi);
    }
}

// ---------------- stage loader (512 threads) ----------------
// Smem rows of 128B (8 x 16B chunks), chunk swizzle: off = r*128 + ((c ^ (r&7))*16).
__device__ __forceinline__ void issue_stage(uint32_t sbase, int kt, int s,
                                            int m0, int n0, int tid) {
    uint32_t base = sbase + s * STAGE_BYTES;
    int k0 = kt * BKB;                       // byte offset into the K dim
    #pragma unroll
    for (int i = 0; i < 2; i++) {            // A: 128 rows x 8 chunks = 1024
        int id = tid + i * 512;
        int r = id >> 3;
        int c = id & 7;
        uint32_t sw = (uint32_t)(r * 128 + ((c ^ (r & 7)) << 4));
        CP_ASYNC16(base + sw,
                   g_xb + (size_t)(m0 + r) * DIM + k0 + c * 16);
    }
    #pragma unroll
    for (int i = 0; i < 4; i++) {            // B: 256 rows x 8 chunks = 2048
        int id = tid + i * 512;
        int r = id >> 3;
        int c = id & 7;
        uint32_t sw = (uint32_t)(r * 128 + ((c ^ (r & 7)) << 4));
        CP_ASYNC16(base + A_BYTES + sw,
                   g_Wb + (size_t)(n0 + r) * DIM + k0 + c * 16);
    }
    CP_COMMIT();
}

// ---------------- fused FP8 QMMA GEMM + softmax-stats -------------------------
// grid (VOCAB/BN=125, NROWS/BM=32), 512 threads, warp grid 4(M) x 4(N), warp tile 32x64
__global__ void __launch_bounds__(512, 1) ce_kernel(const void* yraw) {
    extern __shared__ char smem[];
    __shared__ double s_red[16];
    uint32_t sbase = s2u(smem);

    const int tid = threadIdx.x, warp = tid >> 5, lane = tid & 31;
    const int n0 = blockIdx.x * BN, m0 = blockIdx.y * BM;
    const int wm = (warp >> 2) * 32, wn = (warp & 3) * 64;

    float acc[2][8][4];
    #pragma unroll
    for (int mi = 0; mi < 2; mi++)
        #pragma unroll
        for (int ni = 0; ni < 8; ni++)
            #pragma unroll
            for (int j = 0; j < 4; j++) acc[mi][ni][j] = 0.0f;

    issue_stage(sbase, 0, 0, m0, n0, tid);
    issue_stage(sbase, 1, 1, m0, n0, tid);

    // ldmatrix lane addressing (same byte-level pattern as the fp16 kernel)
    const int a_r = (lane & 15);                       // + wm + 16*mi
    const int a_cbit = (lane >> 4);                    // chunk = 2*ks + a_cbit
    const int b_r = (lane & 7) + ((lane >> 4) << 3);   // + wn + 16*np
    const int b_cbit = ((lane >> 3) & 1);              // chunk = 2*ks + b_cbit

    for (int kt = 0; kt < NKITER; kt++) {
        int s = kt % NSTAGES;
        CP_WAIT1();
        __syncthreads();
        if (kt + 2 < NKITER) issue_stage(sbase, kt + 2, (kt + 2) % NSTAGES, m0, n0, tid);

        uint32_t abase = sbase + s * STAGE_BYTES;
        uint32_t bbase = abase + A_BYTES;
        #pragma unroll
        for (int ks = 0; ks < 4; ks++) {   // each ks = 32 K-bytes = 2 chunks
            uint32_t af[2][4];
            #pragma unroll
            for (int mi = 0; mi < 2; mi++) {
                int r = wm + mi * 16 + a_r;
                int c = ks * 2 + a_cbit;
                ldsm4(af[mi][0], af[mi][1], af[mi][2], af[mi][3],
                      abase + r * 128 + ((c ^ (r & 7)) << 4));
            }
            uint32_t bf[8][2];
            #pragma unroll
            for (int np = 0; np < 4; np++) {
                int r = wn + np * 16 + b_r;
                int c = ks * 2 + b_cbit;
                uint32_t q0, q1, q2, q3;
                ldsm4(q0, q1, q2, q3, bbase + r * 128 + ((c ^ (r & 7)) << 4));
                bf[np * 2][0] = q0;     bf[np * 2][1] = q1;
                bf[np * 2 + 1][0] = q2; bf[np * 2 + 1][1] = q3;
            }
            #pragma unroll
            for (int mi = 0; mi < 2; mi++)
                #pragma unroll
                for (int ni = 0; ni < 8; ni++)
                    mma16832q(acc[mi][ni], af[mi], bf[ni]);
        }
    }

    // ---------------- epilogue from registers ----------------
    // acc[mi][ni]: c0=(r,n) c1=(r,n+1) c2=(r+8,n) c3=(r+8,n+1),
    //   r = wm+16mi+lane/4, n = wn+8ni+2*(lane&3)
    const int ymode = g_ymode;
    float sl = 0.0f;
    #pragma unroll
    for (int mi = 0; mi < 2; mi++) {
        #pragma unroll
        for (int rr = 0; rr < 2; rr++) {
            int row = m0 + wm + mi * 16 + rr * 8 + (lane >> 2);
            long long yv = ymode ? ((const long long*)yraw)[row]
                                 : (long long)((const int*)yraw)[row];
            int jt = (int)yv - (n0 + wn);   // target col within this warp's 64-span
            float se = 0.0f;
            #pragma unroll
            for (int ni = 0; ni < 8; ni++) {
                float v0 = acc[mi][ni][rr * 2];
                float v1 = acc[mi][ni][rr * 2 + 1];
                se += __expf(v0) + __expf(v1);
                sl += v0 + v1;
                int cb = ni * 8 + ((lane & 3) << 1);
                if (cb == jt)     g_tgt[row] = v0;
                if (cb + 1 == jt) g_tgt[row] = v1;
            }
            se += __shfl_xor_sync(0xffffffffu, se, 1);
            se += __shfl_xor_sync(0xffffffffu, se, 2);
            if ((lane & 3) == 0) atomicAdd(&g_rowS[row], se);
        }
    }
    #pragma unroll
    for (int o = 16; o > 0; o >>= 1) sl += __shfl_xor_sync(0xffffffffu, sl, o);
    if (lane == 0) s_red[warp] = (double)sl;
    __syncthreads();
    if (tid == 0) {
        double t = 0.0;
        #pragma unroll
        for (int i = 0; i < 16; i++) t += s_red[i];
        atomicAdd(&g_sumAll, t);
    }
}

// ---------------- finalize: scalar loss ----------------
__global__ void finalize_kernel(float* out) {
    __shared__ double sa[512], sb[512];
    int t = threadIdx.x;
    double a = 0.0, b = 0.0;
    for (int n = t; n < NROWS; n += 512) {
        a += (double)logf(g_rowS[n]);
        b += (double)g_tgt[n];
    }
    sa[t] = a; sb[t] = b;
    __syncthreads();
    for (int o = 256; o > 0; o >>= 1) {
        if (t < o) { sa[t] += sa[t + o]; sb[t] += sb[t + o]; }
        __syncthreads();
    }
    if (t == 0) {
        double loss = sa[0] / (double)NROWS
                    - 0.9 * sb[0] / (double)NROWS
                    - 0.1 * (g_sumAll / ((double)NROWS * (double)VOCAB));
        out[0] = (float)loss;
    }
}

// ---------------- launch ----------------
extern "C" void kernel_launch(void* const* d_in, const int* in_sizes, int n_in,
                              void* d_out, int out_size) {
    const float* x = (const float*)d_in[0];
    const float* W = (const float*)d_in[1];
    const void*  y = d_in[2];

    cudaFuncSetAttribute(ce_kernel, cudaFuncAttributeMaxDynamicSharedMemorySize, SMEM_BYTES);

    init_kernel<<<32, 256>>>(y);
    convert_kernel<<<2048, 256>>>(x, W);
    dim3 grid(VOCAB / BN, NROWS / BM);
    ce_kernel<<<grid, 512, SMEM_BYTES>>>(y);
    finalize_kernel<<<1, 512>>>((float*)d_out);
}

// round 13
// speedup vs baseline: 1.1463x; 1.1463x over previous
#include <cuda_runtime.h>
#include <cuda_fp16.h>
#include <cstdint>
#include <math.h>

// ---------------- problem constants ----------------
#define NROWS 4096
#define DIM   1024
#define VOCAB 32000

// ---------------- tiling ----------------
#define BM 256
#define BN 256
#define BK 64
#define NKITER (DIM / BK)         // 16
#define NSTAGES 3
#define A_BYTES (BM * BK * 2)     // 32768
#define STAGE_BYTES (2 * A_BYTES) // 65536 (A + B)
#define SMEM_BYTES (NSTAGES * STAGE_BYTES)  // 196608

// ---------------- device scratch (allocation-free rule) ----------------
__device__ __half g_xb[(size_t)NROWS * DIM];   // 8 MB, row-major
__device__ __half g_Wb[(size_t)VOCAB * DIM];   // 64 MB, row-major
__device__ float  g_rowS[NROWS];
__device__ float  g_tgt[NROWS];
__device__ double g_sumAll;
__device__ int    g_ymode;

// ---------------- PTX helpers ----------------
__device__ __forceinline__ uint32_t s2u(const void* p) {
    uint32_t a;
    asm("{ .reg .u64 t; cvta.to.shared.u64 t, %1; cvt.u32.u64 %0, t; }" : "=r"(a) : "l"(p));
    return a;
}

#define CP_ASYNC16(dst, src) \
    asm volatile("cp.async.cg.shared.global [%0], [%1], 16;" :: "r"(dst), "l"(src))
#define CP_COMMIT()  asm volatile("cp.async.commit_group;" ::: "memory")
#define CP_WAIT1()   asm volatile("cp.async.wait_group 1;"  ::: "memory")

__device__ __forceinline__ void ldsm4(uint32_t& r0, uint32_t& r1, uint32_t& r2, uint32_t& r3,
                                      uint32_t addr) {
    asm volatile("ldmatrix.sync.aligned.m8n8.x4.shared.b16 {%0,%1,%2,%3}, [%4];"
                 : "=r"(r0), "=r"(r1), "=r"(r2), "=r"(r3) : "r"(addr));
}

// fp16 accumulate: 2 acc regs, each packing 2 halves.
// c[0] = halves {(r,n), (r,n+1)};  c[1] = halves {(r+8,n), (r+8,n+1)}
__device__ __forceinline__ void mma16816h(uint32_t* c, const uint32_t* a, const uint32_t* b) {
    asm volatile(
        "mma.sync.aligned.m16n8k16.row.col.f16.f16.f16.f16 "
        "{%0,%1}, {%2,%3,%4,%5}, {%6,%7}, {%0,%1};"
        : "+r"(c[0]), "+r"(c[1])
        : "r"(a[0]), "r"(a[1]), "r"(a[2]), "r"(a[3]), "r"(b[0]), "r"(b[1]));
}

// ---------------- init: zero accumulators + detect y dtype ----------------
__global__ void init_kernel(const void* yraw) {
    int t = blockIdx.x * blockDim.x + threadIdx.x;
    for (int j = t; j < NROWS; j += gridDim.x * blockDim.x) g_rowS[j] = 0.0f;
    if (blockIdx.x == 0) {
        __shared__ int bad;
        if (threadIdx.x == 0) { bad = 0; g_sumAll = 0.0; }
        __syncthreads();
        const long long* y64 = (const long long*)yraw;
        for (int j = threadIdx.x; j < 2048; j += blockDim.x) {
            long long v = y64[j];
            if (v < 0 || v >= VOCAB) bad = 1;
        }
        __syncthreads();
        if (threadIdx.x == 0) g_ymode = bad ? 0 : 1;
    }
}

// ---------------- convert fp32 -> fp16 (row-major) ----------------
__global__ void convert_kernel(const float* __restrict__ x, const float* __restrict__ W) {
    long long i = (long long)blockIdx.x * blockDim.x + threadIdx.x;
    long long stride = (long long)gridDim.x * blockDim.x;
    const long long NX2 = (long long)NROWS * DIM / 2;
    const long long NW2 = (long long)VOCAB * DIM / 2;
    for (long long j = i; j < NX2; j += stride) {
        float2 v = ((const float2*)x)[j];
        ((__half2*)g_xb)[j] = __floats2half2_rn(v.x, v.y);
    }
    for (long long j = i; j < NW2; j += stride) {
        float2 v = ((const float2*)W)[j];
        ((__half2*)g_Wb)[j] = __floats2half2_rn(v.x, v.y);
    }
}

// ---------------- stage loader halves (512 threads) ----------------
// Tile smem layout: row r (0..255), 16B-chunk c (0..7); byte off = r*128 + ((c ^ (r&7))*16).
__device__ __forceinline__ void issue_stage_A(uint32_t sbase, int kt, int s,
                                              int m0, int tid) {
    uint32_t base = sbase + s * STAGE_BYTES;
    int k0 = kt * BK;
    #pragma unroll
    for (int i = 0; i < 4; i++) {
        int id = tid + i * 512;            // 0..2047
        int r = id >> 3;                   // 0..255
        int c = id & 7;
        uint32_t sw = (uint32_t)(r * 128 + ((c ^ (r & 7)) << 4));
        CP_ASYNC16(base + sw,
                   (const char*)g_xb + ((size_t)(m0 + r) * DIM + k0 + c * 8) * 2);
    }
}
__device__ __forceinline__ void issue_stage_B(uint32_t sbase, int kt, int s,
                                              int n0, int tid) {
    uint32_t base = sbase + s * STAGE_BYTES + A_BYTES;
    int k0 = kt * BK;
    #pragma unroll
    for (int i = 0; i < 4; i++) {
        int id = tid + i * 512;
        int r = id >> 3;
        int c = id & 7;
        uint32_t sw = (uint32_t)(r * 128 + ((c ^ (r & 7)) << 4));
        CP_ASYNC16(base + sw,
                   (const char*)g_Wb + ((size_t)(n0 + r) * DIM + k0 + c * 8) * 2);
    }
}

// ---------------- fused HMMA GEMM + softmax-stats -----------------------------
// grid (VOCAB/BN=125, NROWS/BM=16), 512 threads, warp grid 4(M) x 4(N), warp tile 64x64
// Identical to the 692us round-11 kernel EXCEPT cp.async issue for stage kt+2 is
// split and interleaved between ks compute blocks (off the barrier-exit path).
__global__ void __launch_bounds__(512, 1) ce_kernel(const void* yraw) {
    extern __shared__ char smem[];
    __shared__ double s_red[16];
    uint32_t sbase = s2u(smem);

    const int tid = threadIdx.x, warp = tid >> 5, lane = tid & 31;
    const int n0 = blockIdx.x * BN, m0 = blockIdx.y * BM;
    const int wm = (warp >> 2) * 64, wn = (warp & 3) * 64;

    uint32_t acc[4][8][2];
    #pragma unroll
    for (int mi = 0; mi < 4; mi++)
        #pragma unroll
        for (int ni = 0; ni < 8; ni++) { acc[mi][ni][0] = 0u; acc[mi][ni][1] = 0u; }

    issue_stage_A(sbase, 0, 0, m0, tid);
    issue_stage_B(sbase, 0, 0, n0, tid);
    CP_COMMIT();
    issue_stage_A(sbase, 1, 1, m0, tid);
    issue_stage_B(sbase, 1, 1, n0, tid);
    CP_COMMIT();

    // precomputed ldmatrix lane addressing
    const int a_r = (lane & 15);            // + wm + 16*mi
    const int a_cbit = (lane >> 4);         // +2*ks
    const int b_r = (lane & 7) + ((lane >> 4) << 3);   // + wn + 16*np
    const int b_cbit = ((lane >> 3) & 1);   // +2*ks

    for (int kt = 0; kt < NKITER; kt++) {
        int s = kt % NSTAGES;
        CP_WAIT1();
        __syncthreads();
        const bool pf = (kt + 2 < NKITER);
        const int sn = (kt + 2) % NSTAGES;

        uint32_t abase = sbase + s * STAGE_BYTES;
        uint32_t bbase = abase + A_BYTES;
        #pragma unroll
        for (int ks = 0; ks < 4; ks++) {
            uint32_t af[4][4];
            #pragma unroll
            for (int mi = 0; mi < 4; mi++) {
                int r = wm + mi * 16 + a_r;
                int c = ks * 2 + a_cbit;
                ldsm4(af[mi][0], af[mi][1], af[mi][2], af[mi][3],
                      abase + r * 128 + ((c ^ (r & 7)) << 4));
            }
            uint32_t bf[8][2];
            #pragma unroll
            for (int np = 0; np < 4; np++) {
                int r = wn + np * 16 + b_r;
                int c = ks * 2 + b_cbit;
                uint32_t q0, q1, q2, q3;
                ldsm4(q0, q1, q2, q3, bbase + r * 128 + ((c ^ (r & 7)) << 4));
                bf[np * 2][0] = q0;     bf[np * 2][1] = q1;
                bf[np * 2 + 1][0] = q2; bf[np * 2 + 1][1] = q3;
            }
            #pragma unroll
            for (int mi = 0; mi < 4; mi++)
                #pragma unroll
                for (int ni = 0; ni < 8; ni++)
                    mma16816h(acc[mi][ni], af[mi], bf[ni]);

            // interleaved prefetch of stage kt+2: A-half after ks=0, B-half after ks=1
            if (ks == 0 && pf) issue_stage_A(sbase, kt + 2, sn, m0, tid);
            if (ks == 1 && pf) { issue_stage_B(sbase, kt + 2, sn, n0, tid); CP_COMMIT(); }
        }
    }

    // ---------------- epilogue from registers ----------------
    // acc[mi][ni][rr] packs halves {(r + 8rr, n), (r + 8rr, n+1)},
    //   r = wm+16mi+lane/4, n = wn+8ni+2*(lane&3)
    const int ymode = g_ymode;
    float sl = 0.0f;
    #pragma unroll
    for (int mi = 0; mi < 4; mi++) {
        #pragma unroll
        for (int rr = 0; rr < 2; rr++) {
            int row = m0 + wm + mi * 16 + rr * 8 + (lane >> 2);
            long long yv = ymode ? ((const long long*)yraw)[row]
                                 : (long long)((const int*)yraw)[row];
            int jt = (int)yv - (n0 + wn);   // target col within this warp's 64-span
            float se = 0.0f;
            #pragma unroll
            for (int ni = 0; ni < 8; ni++) {
                float2 v = __half22float2(*(const __half2*)&acc[mi][ni][rr]);
                se += __expf(v.x) + __expf(v.y);
                sl += v.x + v.y;
                int cb = ni * 8 + ((lane & 3) << 1);
                if (cb == jt)     g_tgt[row] = v.x;
                if (cb + 1 == jt) g_tgt[row] = v.y;
            }
            se += __shfl_xor_sync(0xffffffffu, se, 1);
            se += __shfl_xor_sync(0xffffffffu, se, 2);
            if ((lane & 3) == 0) atomicAdd(&g_rowS[row], se);
        }
    }
    #pragma unroll
    for (int o = 16; o > 0; o >>= 1) sl += __shfl_xor_sync(0xffffffffu, sl, o);
    if (lane == 0) s_red[warp] = (double)sl;
    __syncthreads();
    if (tid == 0) {
        double t = 0.0;
        #pragma unroll
        for (int i = 0; i < 16; i++) t += s_red[i];
        atomicAdd(&g_sumAll, t);
    }
}

// ---------------- finalize: scalar loss ----------------
__global__ void finalize_kernel(float* out) {
    __shared__ double sa[512], sb[512];
    int t = threadIdx.x;
    double a = 0.0, b = 0.0;
    for (int n = t; n < NROWS; n += 512) {
        a += (double)logf(g_rowS[n]);
        b += (double)g_tgt[n];
    }
    sa[t] = a; sb[t] = b;
    __syncthreads();
    for (int o = 256; o > 0; o >>= 1) {
        if (t < o) { sa[t] += sa[t + o]; sb[t] += sb[t + o]; }
        __syncthreads();
    }
    if (t == 0) {
        double loss = sa[0] / (double)NROWS
                    - 0.9 * sb[0] / (double)NROWS
                    - 0.1 * (g_sumAll / ((double)NROWS * (double)VOCAB));
        out[0] = (float)loss;
    }
}

// ---------------- launch ----------------
extern "C" void kernel_launch(void* const* d_in, const int* in_sizes, int n_in,
                              void* d_out, int out_size) {
    const float* x = (const float*)d_in[0];
    const float* W = (const float*)d_in[1];
    const void*  y = d_in[2];

    cudaFuncSetAttribute(ce_kernel, cudaFuncAttributeMaxDynamicSharedMemorySize, SMEM_BYTES);

    init_kernel<<<32, 256>>>(y);
    convert_kernel<<<2048, 256>>>(x, W);
    dim3 grid(VOCAB / BN, NROWS / BM);
    ce_kernel<<<grid, 512, SMEM_BYTES>>>(y);
    finalize_kernel<<<1, 512>>>((float*)d_out);
}

// round 14
// speedup vs baseline: 1.1750x; 1.0250x over previous
#include <cuda_runtime.h>
#include <cuda_fp16.h>
#include <cstdint>
#include <math.h>

// ---------------- problem constants ----------------
#define NROWS 4096
#define DIM   1024
#define VOCAB 32000

// ---------------- tiling ----------------
#define BM 256
#define BN 256
#define BK 64
#define NKITER (DIM / BK)         // 16
#define NSTAGES 3
#define A_BYTES (BM * BK * 2)     // 32768
#define STAGE_BYTES (2 * A_BYTES) // 65536 (A + B)
#define SMEM_BYTES (NSTAGES * STAGE_BYTES)  // 196608

// ---------------- device scratch (allocation-free rule) ----------------
__device__ __half g_xb[(size_t)NROWS * DIM];   // 8 MB, row-major
__device__ __half g_Wb[(size_t)VOCAB * DIM];   // 64 MB, row-major
__device__ float  g_rowS[NROWS];
__device__ float  g_tgt[NROWS];
__device__ double g_sumAll;
__device__ int    g_ymode;

// ---------------- PTX helpers ----------------
__device__ __forceinline__ uint32_t s2u(const void* p) {
    uint32_t a;
    asm("{ .reg .u64 t; cvta.to.shared.u64 t, %1; cvt.u32.u64 %0, t; }" : "=r"(a) : "l"(p));
    return a;
}

#define CP_ASYNC16(dst, src) \
    asm volatile("cp.async.cg.shared.global [%0], [%1], 16;" :: "r"(dst), "l"(src))
#define CP_COMMIT()  asm volatile("cp.async.commit_group;" ::: "memory")
#define CP_WAIT1()   asm volatile("cp.async.wait_group 1;"  ::: "memory")

__device__ __forceinline__ void ldsm4(uint32_t& r0, uint32_t& r1, uint32_t& r2, uint32_t& r3,
                                      uint32_t addr) {
    asm volatile("ldmatrix.sync.aligned.m8n8.x4.shared.b16 {%0,%1,%2,%3}, [%4];"
                 : "=r"(r0), "=r"(r1), "=r"(r2), "=r"(r3) : "r"(addr));
}

// fp16 accumulate: 2 acc regs, each packing 2 halves.
// c[0] = halves {(r,n), (r,n+1)};  c[1] = halves {(r+8,n), (r+8,n+1)}
__device__ __forceinline__ void mma16816h(uint32_t* c, const uint32_t* a, const uint32_t* b) {
    asm volatile(
        "mma.sync.aligned.m16n8k16.row.col.f16.f16.f16.f16 "
        "{%0,%1}, {%2,%3,%4,%5}, {%6,%7}, {%0,%1};"
        : "+r"(c[0]), "+r"(c[1])
        : "r"(a[0]), "r"(a[1]), "r"(a[2]), "r"(a[3]), "r"(b[0]), "r"(b[1]));
}

// ---------------- convert fp32 -> fp16 + init (fused; convert-side fusion is
// proven safe — the R5-R7 regression was the ce-side last-CTA tail, not this) --
__global__ void convert_kernel(const float* __restrict__ x, const float* __restrict__ W,
                               const void* yraw) {
    long long i = (long long)blockIdx.x * blockDim.x + threadIdx.x;
    long long stride = (long long)gridDim.x * blockDim.x;
    const long long NX2 = (long long)NROWS * DIM / 2;
    const long long NW2 = (long long)VOCAB * DIM / 2;
    for (long long j = i; j < NX2; j += stride) {
        float2 v = ((const float2*)x)[j];
        ((__half2*)g_xb)[j] = __floats2half2_rn(v.x, v.y);
    }
    for (long long j = i; j < NW2; j += stride) {
        float2 v = ((const float2*)W)[j];
        ((__half2*)g_Wb)[j] = __floats2half2_rn(v.x, v.y);
    }
    // fused init (completes before ce_kernel by stream order)
    if (blockIdx.x == 0) {
        for (int j = threadIdx.x; j < NROWS; j += blockDim.x) g_rowS[j] = 0.0f;
        __shared__ int bad;
        if (threadIdx.x == 0) { bad = 0; g_sumAll = 0.0; }
        __syncthreads();
        const long long* y64 = (const long long*)yraw;
        for (int j = threadIdx.x; j < 2048; j += blockDim.x) {
            long long v = y64[j];
            if (v < 0 || v >= VOCAB) bad = 1;
        }
        __syncthreads();
        if (threadIdx.x == 0) g_ymode = bad ? 0 : 1;
    }
}

// ---------------- stage loader (512 threads) ----------------
// Tile smem layout: row r (0..255), 16B-chunk c (0..7); byte off = r*128 + ((c ^ (r&7))*16).
__device__ __forceinline__ void issue_stage(uint32_t sbase, int kt, int s,
                                            int m0, int n0, int tid) {
    uint32_t base = sbase + s * STAGE_BYTES;
    int k0 = kt * BK;
    #pragma unroll
    for (int i = 0; i < 4; i++) {
        int id = tid + i * 512;            // 0..2047
        int r = id >> 3;                   // 0..255
        int c = id & 7;
        uint32_t sw = (uint32_t)(r * 128 + ((c ^ (r & 7)) << 4));
        CP_ASYNC16(base + sw,
                   (const char*)g_xb + ((size_t)(m0 + r) * DIM + k0 + c * 8) * 2);
        CP_ASYNC16(base + A_BYTES + sw,
                   (const char*)g_Wb + ((size_t)(n0 + r) * DIM + k0 + c * 8) * 2);
    }
    CP_COMMIT();
}

// ---------------- fused HMMA GEMM + softmax-stats -----------------------------
// grid (VOCAB/BN=125, NROWS/BM=16), 512 threads, warp grid 4(M) x 4(N), warp tile 64x64
// fp16 inputs AND fp16 accumulation; 256x256 CTA tile. (Best config: round 11.)
__global__ void __launch_bounds__(512, 1) ce_kernel(const void* yraw) {
    extern __shared__ char smem[];
    __shared__ double s_red[16];
    uint32_t sbase = s2u(smem);

    const int tid = threadIdx.x, warp = tid >> 5, lane = tid & 31;
    const int n0 = blockIdx.x * BN, m0 = blockIdx.y * BM;
    const int wm = (warp >> 2) * 64, wn = (warp & 3) * 64;

    uint32_t acc[4][8][2];
    #pragma unroll
    for (int mi = 0; mi < 4; mi++)
        #pragma unroll
        for (int ni = 0; ni < 8; ni++) { acc[mi][ni][0] = 0u; acc[mi][ni][1] = 0u; }

    issue_stage(sbase, 0, 0, m0, n0, tid);
    issue_stage(sbase, 1, 1, m0, n0, tid);

    // precomputed ldmatrix lane addressing
    const int a_r = (lane & 15);            // + wm + 16*mi
    const int a_cbit = (lane >> 4);         // +2*ks
    const int b_r = (lane & 7) + ((lane >> 4) << 3);   // + wn + 16*np
    const int b_cbit = ((lane >> 3) & 1);   // +2*ks

    for (int kt = 0; kt < NKITER; kt++) {
        int s = kt % NSTAGES;
        CP_WAIT1();
        __syncthreads();
        if (kt + 2 < NKITER) issue_stage(sbase, kt + 2, (kt + 2) % NSTAGES, m0, n0, tid);

        uint32_t abase = sbase + s * STAGE_BYTES;
        uint32_t bbase = abase + A_BYTES;
        #pragma unroll
        for (int ks = 0; ks < 4; ks++) {
            uint32_t af[4][4];
            #pragma unroll
            for (int mi = 0; mi < 4; mi++) {
                int r = wm + mi * 16 + a_r;
                int c = ks * 2 + a_cbit;
                ldsm4(af[mi][0], af[mi][1], af[mi][2], af[mi][3],
                      abase + r * 128 + ((c ^ (r & 7)) << 4));
            }
            uint32_t bf[8][2];
            #pragma unroll
            for (int np = 0; np < 4; np++) {
                int r = wn + np * 16 + b_r;
                int c = ks * 2 + b_cbit;
                uint32_t q0, q1, q2, q3;
                ldsm4(q0, q1, q2, q3, bbase + r * 128 + ((c ^ (r & 7)) << 4));
                bf[np * 2][0] = q0;     bf[np * 2][1] = q1;
                bf[np * 2 + 1][0] = q2; bf[np * 2 + 1][1] = q3;
            }
            #pragma unroll
            for (int mi = 0; mi < 4; mi++)
                #pragma unroll
                for (int ni = 0; ni < 8; ni++)
                    mma16816h(acc[mi][ni], af[mi], bf[ni]);
        }
    }

    // ---------------- epilogue from registers ----------------
    // acc[mi][ni][rr] packs halves {(r + 8rr, n), (r + 8rr, n+1)},
    //   r = wm+16mi+lane/4, n = wn+8ni+2*(lane&3)
    const int ymode = g_ymode;
    float sl = 0.0f;
    #pragma unroll
    for (int mi = 0; mi < 4; mi++) {
        #pragma unroll
        for (int rr = 0; rr < 2; rr++) {
            int row = m0 + wm + mi * 16 + rr * 8 + (lane >> 2);
            long long yv = ymode ? ((const long long*)yraw)[row]
                                 : (long long)((const int*)yraw)[row];
            int jt = (int)yv - (n0 + wn);   // target col within this warp's 64-span
            float se = 0.0f;
            #pragma unroll
            for (int ni = 0; ni < 8; ni++) {
                float2 v = __half22float2(*(const __half2*)&acc[mi][ni][rr]);
                se += __expf(v.x) + __expf(v.y);
                sl += v.x + v.y;
                int cb = ni * 8 + ((lane & 3) << 1);
                if (cb == jt)     g_tgt[row] = v.x;
                if (cb + 1 == jt) g_tgt[row] = v.y;
            }
            se += __shfl_xor_sync(0xffffffffu, se, 1);
            se += __shfl_xor_sync(0xffffffffu, se, 2);
            if ((lane & 3) == 0) atomicAdd(&g_rowS[row], se);
        }
    }
    #pragma unroll
    for (int o = 16; o > 0; o >>= 1) sl += __shfl_xor_sync(0xffffffffu, sl, o);
    if (lane == 0) s_red[warp] = (double)sl;
    __syncthreads();
    if (tid == 0) {
        double t = 0.0;
        #pragma unroll
        for (int i = 0; i < 16; i++) t += s_red[i];
        atomicAdd(&g_sumAll, t);
    }
}

// ---------------- finalize: scalar loss (separate launch — R8 rule) -----------
__global__ void finalize_kernel(float* out) {
    __shared__ double sa[512], sb[512];
    int t = threadIdx.x;
    double a = 0.0, b = 0.0;
    for (int n = t; n < NROWS; n += 512) {
        a += (double)logf(g_rowS[n]);
        b += (double)g_tgt[n];
    }
    sa[t] = a; sb[t] = b;
    __syncthreads();
    for (int o = 256; o > 0; o >>= 1) {
        if (t < o) { sa[t] += sa[t + o]; sb[t] += sb[t + o]; }
        __syncthreads();
    }
    if (t == 0) {
        double loss = sa[0] / (double)NROWS
                    - 0.9 * sb[0] / (double)NROWS
                    - 0.1 * (g_sumAll / ((double)NROWS * (double)VOCAB));
        out[0] = (float)loss;
    }
}

// ---------------- launch ----------------
extern "C" void kernel_launch(void* const* d_in, const int* in_sizes, int n_in,
                              void* d_out, int out_size) {
    const float* x = (const float*)d_in[0];
    const float* W = (const float*)d_in[1];
    const void*  y = d_in[2];

    cudaFuncSetAttribute(ce_kernel, cudaFuncAttributeMaxDynamicSharedMemorySize, SMEM_BYTES);

    convert_kernel<<<2048, 256>>>(x, W, y);
    dim3 grid(VOCAB / BN, NROWS / BM);
    ce_kernel<<<grid, 512, SMEM_BYTES>>>(y);
    finalize_kernel<<<1, 512>>>((float*)d_out);
}

// round 15
// speedup vs baseline: 1.1828x; 1.0067x over previous
#include <cuda_runtime.h>
#include <cuda_fp16.h>
#include <cstdint>
#include <math.h>

// ---------------- problem constants ----------------
#define NROWS 4096
#define DIM   1024
#define VOCAB 32000

// ---------------- tiling ----------------
#define BM 256
#define BN 256
#define BK 64
#define NKITER (DIM / BK)         // 16
#define NSTAGES 3
#define A_BYTES (BM * BK * 2)     // 32768
#define STAGE_BYTES (2 * A_BYTES) // 65536 (A + B)
#define SMEM_BYTES (NSTAGES * STAGE_BYTES)  // 196608

// ---------------- device scratch (allocation-free rule) ----------------
__device__ __half g_xb[(size_t)NROWS * DIM];   // 8 MB, row-major
__device__ __half g_Wb[(size_t)VOCAB * DIM];   // 64 MB, row-major
__device__ float  g_rowS[NROWS];
__device__ float  g_tgt[NROWS];
__device__ double g_sumAll;
__device__ int    g_ymode;

// ---------------- PTX helpers ----------------
__device__ __forceinline__ uint32_t s2u(const void* p) {
    uint32_t a;
    asm("{ .reg .u64 t; cvta.to.shared.u64 t, %1; cvt.u32.u64 %0, t; }" : "=r"(a) : "l"(p));
    return a;
}

#define CP_ASYNC16(dst, src) \
    asm volatile("cp.async.cg.shared.global [%0], [%1], 16;" :: "r"(dst), "l"(src))
#define CP_COMMIT()  asm volatile("cp.async.commit_group;" ::: "memory")
#define CP_WAIT1()   asm volatile("cp.async.wait_group 1;"  ::: "memory")

__device__ __forceinline__ void ldsm4(uint32_t& r0, uint32_t& r1, uint32_t& r2, uint32_t& r3,
                                      uint32_t addr) {
    asm volatile("ldmatrix.sync.aligned.m8n8.x4.shared.b16 {%0,%1,%2,%3}, [%4];"
                 : "=r"(r0), "=r"(r1), "=r"(r2), "=r"(r3) : "r"(addr));
}

// fp16 accumulate: 2 acc regs, each packing 2 halves.
// c[0] = halves {(r,n), (r,n+1)};  c[1] = halves {(r+8,n), (r+8,n+1)}
__device__ __forceinline__ void mma16816h(uint32_t* c, const uint32_t* a, const uint32_t* b) {
    asm volatile(
        "mma.sync.aligned.m16n8k16.row.col.f16.f16.f16.f16 "
        "{%0,%1}, {%2,%3,%4,%5}, {%6,%7}, {%0,%1};"
        : "+r"(c[0]), "+r"(c[1])
        : "r"(a[0]), "r"(a[1]), "r"(a[2]), "r"(a[3]), "r"(b[0]), "r"(b[1]));
}

// ---------------- convert fp32 -> fp16 + init (fused) ----------------
// Wide form: 2x float4 loads (32B, evict-first) -> uint4 store (16B).
__device__ __forceinline__ void conv8(const float* __restrict__ src,
                                      __half* __restrict__ dst,
                                      long long nelem, long long i, long long stride) {
    const long long n8 = nelem >> 3;
    const float4* s4 = (const float4*)src;
    for (long long j = i; j < n8; j += stride) {
        float4 a = __ldcs(&s4[2 * j]);
        float4 b = __ldcs(&s4[2 * j + 1]);
        __half2 h0 = __floats2half2_rn(a.x, a.y);
        __half2 h1 = __floats2half2_rn(a.z, a.w);
        __half2 h2 = __floats2half2_rn(b.x, b.y);
        __half2 h3 = __floats2half2_rn(b.z, b.w);
        uint4 o;
        o.x = *(uint32_t*)&h0; o.y = *(uint32_t*)&h1;
        o.z = *(uint32_t*)&h2; o.w = *(uint32_t*)&h3;
        ((uint4*)dst)[j] = o;
    }
}

__global__ void convert_kernel(const float* __restrict__ x, const float* __restrict__ W,
                               const void* yraw) {
    long long i = (long long)blockIdx.x * blockDim.x + threadIdx.x;
    long long stride = (long long)gridDim.x * blockDim.x;
    conv8(x, g_xb, (long long)NROWS * DIM, i, stride);
    conv8(W, g_Wb, (long long)VOCAB * DIM, i, stride);
    // fused init (completes before ce_kernel by stream order)
    if (blockIdx.x == 0) {
        for (int j = threadIdx.x; j < NROWS; j += blockDim.x) g_rowS[j] = 0.0f;
        __shared__ int bad;
        if (threadIdx.x == 0) { bad = 0; g_sumAll = 0.0; }
        __syncthreads();
        const long long* y64 = (const long long*)yraw;
        for (int j = threadIdx.x; j < 2048; j += blockDim.x) {
            long long v = y64[j];
            if (v < 0 || v >= VOCAB) bad = 1;
        }
        __syncthreads();
        if (threadIdx.x == 0) g_ymode = bad ? 0 : 1;
    }
}

// ---------------- stage loader (512 threads) ----------------
// Tile smem layout: row r (0..255), 16B-chunk c (0..7); byte off = r*128 + ((c ^ (r&7))*16).
__device__ __forceinline__ void issue_stage(uint32_t sbase, int kt, int s,
                                            int m0, int n0, int tid) {
    uint32_t base = sbase + s * STAGE_BYTES;
    int k0 = kt * BK;
    #pragma unroll
    for (int i = 0; i < 4; i++) {
        int id = tid + i * 512;            // 0..2047
        int r = id >> 3;                   // 0..255
        int c = id & 7;
        uint32_t sw = (uint32_t)(r * 128 + ((c ^ (r & 7)) << 4));
        CP_ASYNC16(base + sw,
                   (const char*)g_xb + ((size_t)(m0 + r) * DIM + k0 + c * 8) * 2);
        CP_ASYNC16(base + A_BYTES + sw,
                   (const char*)g_Wb + ((size_t)(n0 + r) * DIM + k0 + c * 8) * 2);
    }
    CP_COMMIT();
}

// ---------------- fused HMMA GEMM + softmax-stats -----------------------------
// grid (VOCAB/BN=125, NROWS/BM=16), 512 threads, warp grid 4(M) x 4(N), warp tile 64x64
// fp16 inputs AND fp16 accumulation; 256x256 CTA tile. (Best config: rounds 11/14.)
__global__ void __launch_bounds__(512, 1) ce_kernel(const void* yraw) {
    extern __shared__ char smem[];
    __shared__ double s_red[16];
    uint32_t sbase = s2u(smem);

    const int tid = threadIdx.x, warp = tid >> 5, lane = tid & 31;
    const int n0 = blockIdx.x * BN, m0 = blockIdx.y * BM;
    const int wm = (warp >> 2) * 64, wn = (warp & 3) * 64;

    uint32_t acc[4][8][2];
    #pragma unroll
    for (int mi = 0; mi < 4; mi++)
        #pragma unroll
        for (int ni = 0; ni < 8; ni++) { acc[mi][ni][0] = 0u; acc[mi][ni][1] = 0u; }

    issue_stage(sbase, 0, 0, m0, n0, tid);
    issue_stage(sbase, 1, 1, m0, n0, tid);

    // precomputed ldmatrix lane addressing
    const int a_r = (lane & 15);            // + wm + 16*mi
    const int a_cbit = (lane >> 4);         // +2*ks
    const int b_r = (lane & 7) + ((lane >> 4) << 3);   // + wn + 16*np
    const int b_cbit = ((lane >> 3) & 1);   // +2*ks

    for (int kt = 0; kt < NKITER; kt++) {
        int s = kt % NSTAGES;
        CP_WAIT1();
        __syncthreads();
        if (kt + 2 < NKITER) issue_stage(sbase, kt + 2, (kt + 2) % NSTAGES, m0, n0, tid);

        uint32_t abase = sbase + s * STAGE_BYTES;
        uint32_t bbase = abase + A_BYTES;
        #pragma unroll
        for (int ks = 0; ks < 4; ks++) {
            uint32_t af[4][4];
            #pragma unroll
            for (int mi = 0; mi < 4; mi++) {
                int r = wm + mi * 16 + a_r;
                int c = ks * 2 + a_cbit;
                ldsm4(af[mi][0], af[mi][1], af[mi][2], af[mi][3],
                      abase + r * 128 + ((c ^ (r & 7)) << 4));
            }
            uint32_t bf[8][2];
            #pragma unroll
            for (int np = 0; np < 4; np++) {
                int r = wn + np * 16 + b_r;
                int c = ks * 2 + b_cbit;
                uint32_t q0, q1, q2, q3;
                ldsm4(q0, q1, q2, q3, bbase + r * 128 + ((c ^ (r & 7)) << 4));
                bf[np * 2][0] = q0;     bf[np * 2][1] = q1;
                bf[np * 2 + 1][0] = q2; bf[np * 2 + 1][1] = q3;
            }
            #pragma unroll
            for (int mi = 0; mi < 4; mi++)
                #pragma unroll
                for (int ni = 0; ni < 8; ni++)
                    mma16816h(acc[mi][ni], af[mi], bf[ni]);
        }
    }

    // ---------------- epilogue from registers ----------------
    // acc[mi][ni][rr] packs halves {(r + 8rr, n), (r + 8rr, n+1)},
    //   r = wm+16mi+lane/4, n = wn+8ni+2*(lane&3)
    const int ymode = g_ymode;
    float sl = 0.0f;
    #pragma unroll
    for (int mi = 0; mi < 4; mi++) {
        #pragma unroll
        for (int rr = 0; rr < 2; rr++) {
            int row = m0 + wm + mi * 16 + rr * 8 + (lane >> 2);
            long long yv = ymode ? ((const long long*)yraw)[row]
                                 : (long long)((const int*)yraw)[row];
            int jt = (int)yv - (n0 + wn);   // target col within this warp's 64-span
            float se = 0.0f;
            #pragma unroll
            for (int ni = 0; ni < 8; ni++) {
                float2 v = __half22float2(*(const __half2*)&acc[mi][ni][rr]);
                se += __expf(v.x) + __expf(v.y);
                sl += v.x + v.y;
                int cb = ni * 8 + ((lane & 3) << 1);
                if (cb == jt)     g_tgt[row] = v.x;
                if (cb + 1 == jt) g_tgt[row] = v.y;
            }
            se += __shfl_xor_sync(0xffffffffu, se, 1);
            se += __shfl_xor_sync(0xffffffffu, se, 2);
            if ((lane & 3) == 0) atomicAdd(&g_rowS[row], se);
        }
    }
    #pragma unroll
    for (int o = 16; o > 0; o >>= 1) sl += __shfl_xor_sync(0xffffffffu, sl, o);
    if (lane == 0) s_red[warp] = (double)sl;
    __syncthreads();
    if (tid == 0) {
        double t = 0.0;
        #pragma unroll
        for (int i = 0; i < 16; i++) t += s_red[i];
        atomicAdd(&g_sumAll, t);
    }
}

// ---------------- finalize: scalar loss (separate launch — R8 rule) -----------
__global__ void finalize_kernel(float* out) {
    __shared__ double sa[512], sb[512];
    int t = threadIdx.x;
    double a = 0.0, b = 0.0;
    for (int n = t; n < NROWS; n += 512) {
        a += (double)logf(g_rowS[n]);
        b += (double)g_tgt[n];
    }
    sa[t] = a; sb[t] = b;
    __syncthreads();
    for (int o = 256; o > 0; o >>= 1) {
        if (t < o) { sa[t] += sa[t + o]; sb[t] += sb[t + o]; }
        __syncthreads();
    }
    if (t == 0) {
        double loss = sa[0] / (double)NROWS
                    - 0.9 * sb[0] / (double)NROWS
                    - 0.1 * (g_sumAll / ((double)NROWS * (double)VOCAB));
        out[0] = (float)loss;
    }
}

// ---------------- launch ----------------
extern "C" void kernel_launch(void* const* d_in, const int* in_sizes, int n_in,
                              void* d_out, int out_size) {
    const float* x = (const float*)d_in[0];
    const float* W = (const float*)d_in[1];
    const void*  y = d_in[2];

    cudaFuncSetAttribute(ce_kernel, cudaFuncAttributeMaxDynamicSharedMemorySize, SMEM_BYTES);

    convert_kernel<<<2048, 256>>>(x, W, y);
    dim3 grid(VOCAB / BN, NROWS / BM);
    ce_kernel<<<grid, 512, SMEM_BYTES>>>(y);
    finalize_kernel<<<1, 512>>>((float*)d_out);
}

// round 16
// speedup vs baseline: 1.1938x; 1.0094x over previous
#include <cuda_runtime.h>
#include <cuda_fp16.h>
#include <cstdint>
#include <math.h>

// ---------------- problem constants ----------------
#define NROWS 4096
#define DIM   1024
#define VOCAB 32000

// ---------------- tiling ----------------
#define BM 256
#define BN 256
#define BK 64
#define NKITER (DIM / BK)         // 16
#define NSTAGES 3
#define A_BYTES (BM * BK * 2)     // 32768
#define STAGE_BYTES (2 * A_BYTES) // 65536 (A + B)
#define SMEM_BYTES (NSTAGES * STAGE_BYTES)  // 196608

#define FIN_BLOCKS 16

// ---------------- device scratch (allocation-free rule) ----------------
__device__ __half g_xb[(size_t)NROWS * DIM];   // 8 MB, row-major
__device__ __half g_Wb[(size_t)VOCAB * DIM];   // 64 MB, row-major
__device__ float  g_rowS[NROWS];
__device__ float  g_tgt[NROWS];
__device__ double g_sumAll;
__device__ double g_fa;          // sum of log(rowS)
__device__ double g_fb;          // sum of target logits
__device__ unsigned int g_fdone; // finalize block counter
__device__ int    g_ymode;

// ---------------- PTX helpers ----------------
__device__ __forceinline__ uint32_t s2u(const void* p) {
    uint32_t a;
    asm("{ .reg .u64 t; cvta.to.shared.u64 t, %1; cvt.u32.u64 %0, t; }" : "=r"(a) : "l"(p));
    return a;
}

#define CP_ASYNC16(dst, src) \
    asm volatile("cp.async.cg.shared.global [%0], [%1], 16;" :: "r"(dst), "l"(src))
#define CP_COMMIT()  asm volatile("cp.async.commit_group;" ::: "memory")
#define CP_WAIT1()   asm volatile("cp.async.wait_group 1;"  ::: "memory")

__device__ __forceinline__ void ldsm4(uint32_t& r0, uint32_t& r1, uint32_t& r2, uint32_t& r3,
                                      uint32_t addr) {
    asm volatile("ldmatrix.sync.aligned.m8n8.x4.shared.b16 {%0,%1,%2,%3}, [%4];"
                 : "=r"(r0), "=r"(r1), "=r"(r2), "=r"(r3) : "r"(addr));
}

// fp16 accumulate: 2 acc regs, each packing 2 halves.
// c[0] = halves {(r,n), (r,n+1)};  c[1] = halves {(r+8,n), (r+8,n+1)}
__device__ __forceinline__ void mma16816h(uint32_t* c, const uint32_t* a, const uint32_t* b) {
    asm volatile(
        "mma.sync.aligned.m16n8k16.row.col.f16.f16.f16.f16 "
        "{%0,%1}, {%2,%3,%4,%5}, {%6,%7}, {%0,%1};"
        : "+r"(c[0]), "+r"(c[1])
        : "r"(a[0]), "r"(a[1]), "r"(a[2]), "r"(a[3]), "r"(b[0]), "r"(b[1]));
}

// ---------------- convert fp32 -> fp16 + init (fused) ----------------
// 16 elems/iter: 4 independent float4 loads (evict-first) -> 2 uint4 stores. MLP=4.
__device__ __forceinline__ void conv16(const float* __restrict__ src,
                                       __half* __restrict__ dst,
                                       long long nelem, long long i, long long stride) {
    const long long n16 = nelem >> 4;
    const float4* s4 = (const float4*)src;
    uint4* d4 = (uint4*)dst;
    for (long long j = i; j < n16; j += stride) {
        float4 a = __ldcs(&s4[4 * j]);
        float4 b = __ldcs(&s4[4 * j + 1]);
        float4 c = __ldcs(&s4[4 * j + 2]);
        float4 d = __ldcs(&s4[4 * j + 3]);
        __half2 h0 = __floats2half2_rn(a.x, a.y), h1 = __floats2half2_rn(a.z, a.w);
        __half2 h2 = __floats2half2_rn(b.x, b.y), h3 = __floats2half2_rn(b.z, b.w);
        __half2 h4 = __floats2half2_rn(c.x, c.y), h5 = __floats2half2_rn(c.z, c.w);
        __half2 h6 = __floats2half2_rn(d.x, d.y), h7 = __floats2half2_rn(d.z, d.w);
        uint4 o0, o1;
        o0.x = *(uint32_t*)&h0; o0.y = *(uint32_t*)&h1;
        o0.z = *(uint32_t*)&h2; o0.w = *(uint32_t*)&h3;
        o1.x = *(uint32_t*)&h4; o1.y = *(uint32_t*)&h5;
        o1.z = *(uint32_t*)&h6; o1.w = *(uint32_t*)&h7;
        d4[2 * j]     = o0;
        d4[2 * j + 1] = o1;
    }
}

__global__ void convert_kernel(const float* __restrict__ x, const float* __restrict__ W,
                               const void* yraw) {
    long long i = (long long)blockIdx.x * blockDim.x + threadIdx.x;
    long long stride = (long long)gridDim.x * blockDim.x;
    conv16(x, g_xb, (long long)NROWS * DIM, i, stride);
    conv16(W, g_Wb, (long long)VOCAB * DIM, i, stride);
    // fused init (completes before ce_kernel by stream order)
    if (blockIdx.x == 0) {
        for (int j = threadIdx.x; j < NROWS; j += blockDim.x) g_rowS[j] = 0.0f;
        __shared__ int bad;
        if (threadIdx.x == 0) {
            bad = 0; g_sumAll = 0.0; g_fa = 0.0; g_fb = 0.0; g_fdone = 0u;
        }
        __syncthreads();
        const long long* y64 = (const long long*)yraw;
        for (int j = threadIdx.x; j < 2048; j += blockDim.x) {
            long long v = y64[j];
            if (v < 0 || v >= VOCAB) bad = 1;
        }
        __syncthreads();
        if (threadIdx.x == 0) g_ymode = bad ? 0 : 1;
    }
}

// ---------------- stage loader (512 threads) ----------------
// Tile smem layout: row r (0..255), 16B-chunk c (0..7); byte off = r*128 + ((c ^ (r&7))*16).
__device__ __forceinline__ void issue_stage(uint32_t sbase, int kt, int s,
                                            int m0, int n0, int tid) {
    uint32_t base = sbase + s * STAGE_BYTES;
    int k0 = kt * BK;
    #pragma unroll
    for (int i = 0; i < 4; i++) {
        int id = tid + i * 512;            // 0..2047
        int r = id >> 3;                   // 0..255
        int c = id & 7;
        uint32_t sw = (uint32_t)(r * 128 + ((c ^ (r & 7)) << 4));
        CP_ASYNC16(base + sw,
                   (const char*)g_xb + ((size_t)(m0 + r) * DIM + k0 + c * 8) * 2);
        CP_ASYNC16(base + A_BYTES + sw,
                   (const char*)g_Wb + ((size_t)(n0 + r) * DIM + k0 + c * 8) * 2);
    }
    CP_COMMIT();
}

// ---------------- fused HMMA GEMM + softmax-stats -----------------------------
// grid (VOCAB/BN=125, NROWS/BM=16), 512 threads, warp grid 4(M) x 4(N), warp tile 64x64
// fp16 inputs AND fp16 accumulation; 256x256 CTA tile. (Best config: rounds 11/14/15.)
__global__ void __launch_bounds__(512, 1) ce_kernel(const void* yraw) {
    extern __shared__ char smem[];
    __shared__ double s_red[16];
    uint32_t sbase = s2u(smem);

    const int tid = threadIdx.x, warp = tid >> 5, lane = tid & 31;
    const int n0 = blockIdx.x * BN, m0 = blockIdx.y * BM;
    const int wm = (warp >> 2) * 64, wn = (warp & 3) * 64;

    uint32_t acc[4][8][2];
    #pragma unroll
    for (int mi = 0; mi < 4; mi++)
        #pragma unroll
        for (int ni = 0; ni < 8; ni++) { acc[mi][ni][0] = 0u; acc[mi][ni][1] = 0u; }

    issue_stage(sbase, 0, 0, m0, n0, tid);
    issue_stage(sbase, 1, 1, m0, n0, tid);

    // precomputed ldmatrix lane addressing
    const int a_r = (lane & 15);            // + wm + 16*mi
    const int a_cbit = (lane >> 4);         // +2*ks
    const int b_r = (lane & 7) + ((lane >> 4) << 3);   // + wn + 16*np
    const int b_cbit = ((lane >> 3) & 1);   // +2*ks

    for (int kt = 0; kt < NKITER; kt++) {
        int s = kt % NSTAGES;
        CP_WAIT1();
        __syncthreads();
        if (kt + 2 < NKITER) issue_stage(sbase, kt + 2, (kt + 2) % NSTAGES, m0, n0, tid);

        uint32_t abase = sbase + s * STAGE_BYTES;
        uint32_t bbase = abase + A_BYTES;
        #pragma unroll
        for (int ks = 0; ks < 4; ks++) {
            uint32_t af[4][4];
            #pragma unroll
            for (int mi = 0; mi < 4; mi++) {
                int r = wm + mi * 16 + a_r;
                int c = ks * 2 + a_cbit;
                ldsm4(af[mi][0], af[mi][1], af[mi][2], af[mi][3],
                      abase + r * 128 + ((c ^ (r & 7)) << 4));
            }
            uint32_t bf[8][2];
            #pragma unroll
            for (int np = 0; np < 4; np++) {
                int r = wn + np * 16 + b_r;
                int c = ks * 2 + b_cbit;
                uint32_t q0, q1, q2, q3;
                ldsm4(q0, q1, q2, q3, bbase + r * 128 + ((c ^ (r & 7)) << 4));
                bf[np * 2][0] = q0;     bf[np * 2][1] = q1;
                bf[np * 2 + 1][0] = q2; bf[np * 2 + 1][1] = q3;
            }
            #pragma unroll
            for (int mi = 0; mi < 4; mi++)
                #pragma unroll
                for (int ni = 0; ni < 8; ni++)
                    mma16816h(acc[mi][ni], af[mi], bf[ni]);
        }
    }

    // ---------------- epilogue from registers ----------------
    // acc[mi][ni][rr] packs halves {(r + 8rr, n), (r + 8rr, n+1)},
    //   r = wm+16mi+lane/4, n = wn+8ni+2*(lane&3)
    const int ymode = g_ymode;
    float sl = 0.0f;
    #pragma unroll
    for (int mi = 0; mi < 4; mi++) {
        #pragma unroll
        for (int rr = 0; rr < 2; rr++) {
            int row = m0 + wm + mi * 16 + rr * 8 + (lane >> 2);
            long long yv = ymode ? ((const long long*)yraw)[row]
                                 : (long long)((const int*)yraw)[row];
            int jt = (int)yv - (n0 + wn);   // target col within this warp's 64-span
            float se = 0.0f;
            #pragma unroll
            for (int ni = 0; ni < 8; ni++) {
                float2 v = __half22float2(*(const __half2*)&acc[mi][ni][rr]);
                se += __expf(v.x) + __expf(v.y);
                sl += v.x + v.y;
                int cb = ni * 8 + ((lane & 3) << 1);
                if (cb == jt)     g_tgt[row] = v.x;
                if (cb + 1 == jt) g_tgt[row] = v.y;
            }
            se += __shfl_xor_sync(0xffffffffu, se, 1);
            se += __shfl_xor_sync(0xffffffffu, se, 2);
            if ((lane & 3) == 0) atomicAdd(&g_rowS[row], se);
        }
    }
    #pragma unroll
    for (int o = 16; o > 0; o >>= 1) sl += __shfl_xor_sync(0xffffffffu, sl, o);
    if (lane == 0) s_red[warp] = (double)sl;
    __syncthreads();
    if (tid == 0) {
        double t = 0.0;
        #pragma unroll
        for (int i = 0; i < 16; i++) t += s_red[i];
        atomicAdd(&g_sumAll, t);
    }
}

// ---------------- finalize: parallel partials + last-block combine ------------
// 16 small blocks at stream-tail: fence cost trivial (no co-resident mainloop).
__global__ void finalize_kernel(float* out) {
    __shared__ double sa[256], sb[256];
    __shared__ int s_last;
    int t = threadIdx.x;
    double a = 0.0, b = 0.0;
    for (int n = blockIdx.x * 256 + t; n < NROWS; n += FIN_BLOCKS * 256) {
        a += (double)logf(g_rowS[n]);
        b += (double)g_tgt[n];
    }
    sa[t] = a; sb[t] = b;
    __syncthreads();
    for (int o = 128; o > 0; o >>= 1) {
        if (t < o) { sa[t] += sa[t + o]; sb[t] += sb[t + o]; }
        __syncthreads();
    }
    if (t == 0) {
        atomicAdd(&g_fa, sa[0]);
        atomicAdd(&g_fb, sb[0]);
        __threadfence();
        unsigned int prev = atomicAdd(&g_fdone, 1u);
        s_last = (prev == FIN_BLOCKS - 1u) ? 1 : 0;
    }
    __syncthreads();
    if (s_last && t == 0) {
        __threadfence();
        double loss = g_fa / (double)NROWS
                    - 0.9 * g_fb / (double)NROWS
                    - 0.1 * (g_sumAll / ((double)NROWS * (double)VOCAB));
        out[0] = (float)loss;
    }
}

// ---------------- launch ----------------
extern "C" void kernel_launch(void* const* d_in, const int* in_sizes, int n_in,
                              void* d_out, int out_size) {
    const float* x = (const float*)d_in[0];
    const float* W = (const float*)d_in[1];
    const void*  y = d_in[2];

    cudaFuncSetAttribute(ce_kernel, cudaFuncAttributeMaxDynamicSharedMemorySize, SMEM_BYTES);

    convert_kernel<<<2048, 256>>>(x, W, y);
    dim3 grid(VOCAB / BN, NROWS / BM);
    ce_kernel<<<grid, 512, SMEM_BYTES>>>(y);
    finalize_kernel<<<FIN_BLOCKS, 256>>>((float*)d_out);
}

// round 17
// speedup vs baseline: 1.2425x; 1.0408x over previous
#include <cuda_runtime.h>
#include <cuda_fp16.h>
#include <cstdint>
#include <math.h>

// ---------------- problem constants ----------------
#define NROWS 4096
#define DIM   1024
#define VOCAB 32000

// ---------------- tiling ----------------
#define BM 128
#define BN 256
#define BK 64
#define NKITER (DIM / BK)          // 16
#define NSTAGES 2
#define A_BYTES (BM * BK * 2)      // 16384
#define B_BYTES (BN * BK * 2)      // 32768
#define STAGE_BYTES (A_BYTES + B_BYTES)     // 49152
#define SMEM_BYTES (NSTAGES * STAGE_BYTES)  // 98304 -> 2 CTAs/SM

#define FIN_BLOCKS 16

// ---------------- device scratch (allocation-free rule) ----------------
__device__ __half g_xb[(size_t)NROWS * DIM];   // 8 MB, row-major
__device__ __half g_Wb[(size_t)VOCAB * DIM];   // 64 MB, row-major
__device__ float  g_rowS[NROWS];
__device__ float  g_tgt[NROWS];
__device__ double g_sumAll;
__device__ double g_fa;
__device__ double g_fb;
__device__ unsigned int g_fdone;
__device__ int    g_ymode;

// ---------------- PTX helpers ----------------
__device__ __forceinline__ uint32_t s2u(const void* p) {
    uint32_t a;
    asm("{ .reg .u64 t; cvta.to.shared.u64 t, %1; cvt.u32.u64 %0, t; }" : "=r"(a) : "l"(p));
    return a;
}

#define CP_ASYNC16(dst, src) \
    asm volatile("cp.async.cg.shared.global [%0], [%1], 16;" :: "r"(dst), "l"(src))
#define CP_COMMIT()  asm volatile("cp.async.commit_group;" ::: "memory")
#define CP_WAIT1()   asm volatile("cp.async.wait_group 1;"  ::: "memory")

__device__ __forceinline__ void ldsm4(uint32_t& r0, uint32_t& r1, uint32_t& r2, uint32_t& r3,
                                      uint32_t addr) {
    asm volatile("ldmatrix.sync.aligned.m8n8.x4.shared.b16 {%0,%1,%2,%3}, [%4];"
                 : "=r"(r0), "=r"(r1), "=r"(r2), "=r"(r3) : "r"(addr));
}

// fp16 accumulate: 2 acc regs, each packing 2 halves.
// c[0] = halves {(r,n), (r,n+1)};  c[1] = halves {(r+8,n), (r+8,n+1)}
__device__ __forceinline__ void mma16816h(uint32_t* c, const uint32_t* a, const uint32_t* b) {
    asm volatile(
        "mma.sync.aligned.m16n8k16.row.col.f16.f16.f16.f16 "
        "{%0,%1}, {%2,%3,%4,%5}, {%6,%7}, {%0,%1};"
        : "+r"(c[0]), "+r"(c[1])
        : "r"(a[0]), "r"(a[1]), "r"(a[2]), "r"(a[3]), "r"(b[0]), "r"(b[1]));
}

// ---------------- convert fp32 -> fp16 + init (fused; unchanged from R16) -----
__device__ __forceinline__ void conv16(const float* __restrict__ src,
                                       __half* __restrict__ dst,
                                       long long nelem, long long i, long long stride) {
    const long long n16 = nelem >> 4;
    const float4* s4 = (const float4*)src;
    uint4* d4 = (uint4*)dst;
    for (long long j = i; j < n16; j += stride) {
        float4 a = __ldcs(&s4[4 * j]);
        float4 b = __ldcs(&s4[4 * j + 1]);
        float4 c = __ldcs(&s4[4 * j + 2]);
        float4 d = __ldcs(&s4[4 * j + 3]);
        __half2 h0 = __floats2half2_rn(a.x, a.y), h1 = __floats2half2_rn(a.z, a.w);
        __half2 h2 = __floats2half2_rn(b.x, b.y), h3 = __floats2half2_rn(b.z, b.w);
        __half2 h4 = __floats2half2_rn(c.x, c.y), h5 = __floats2half2_rn(c.z, c.w);
        __half2 h6 = __floats2half2_rn(d.x, d.y), h7 = __floats2half2_rn(d.z, d.w);
        uint4 o0, o1;
        o0.x = *(uint32_t*)&h0; o0.y = *(uint32_t*)&h1;
        o0.z = *(uint32_t*)&h2; o0.w = *(uint32_t*)&h3;
        o1.x = *(uint32_t*)&h4; o1.y = *(uint32_t*)&h5;
        o1.z = *(uint32_t*)&h6; o1.w = *(uint32_t*)&h7;
        d4[2 * j]     = o0;
        d4[2 * j + 1] = o1;
    }
}

__global__ void convert_kernel(const float* __restrict__ x, const float* __restrict__ W,
                               const void* yraw) {
    long long i = (long long)blockIdx.x * blockDim.x + threadIdx.x;
    long long stride = (long long)gridDim.x * blockDim.x;
    conv16(x, g_xb, (long long)NROWS * DIM, i, stride);
    conv16(W, g_Wb, (long long)VOCAB * DIM, i, stride);
    if (blockIdx.x == 0) {
        for (int j = threadIdx.x; j < NROWS; j += blockDim.x) g_rowS[j] = 0.0f;
        __shared__ int bad;
        if (threadIdx.x == 0) {
            bad = 0; g_sumAll = 0.0; g_fa = 0.0; g_fb = 0.0; g_fdone = 0u;
        }
        __syncthreads();
        const long long* y64 = (const long long*)yraw;
        for (int j = threadIdx.x; j < 2048; j += blockDim.x) {
            long long v = y64[j];
            if (v < 0 || v >= VOCAB) bad = 1;
        }
        __syncthreads();
        if (threadIdx.x == 0) g_ymode = bad ? 0 : 1;
    }
}

// ---------------- stage loader (256 threads) ----------------
// Smem rows of 128B (8 x 16B chunks), chunk swizzle: off = r*128 + ((c ^ (r&7))*16).
__device__ __forceinline__ void issue_stage(uint32_t sbase, int kt, int s,
                                            int m0, int n0, int tid) {
    uint32_t base = sbase + s * STAGE_BYTES;
    int k0 = kt * BK;
    #pragma unroll
    for (int i = 0; i < 4; i++) {            // A: 128 rows x 8 chunks = 1024
        int id = tid + i * 256;
        int r = id >> 3;
        int c = id & 7;
        uint32_t sw = (uint32_t)(r * 128 + ((c ^ (r & 7)) << 4));
        CP_ASYNC16(base + sw,
                   (const char*)g_xb + ((size_t)(m0 + r) * DIM + k0 + c * 8) * 2);
    }
    #pragma unroll
    for (int i = 0; i < 8; i++) {            // B: 256 rows x 8 chunks = 2048
        int id = tid + i * 256;
        int r = id >> 3;
        int c = id & 7;
        uint32_t sw = (uint32_t)(r * 128 + ((c ^ (r & 7)) << 4));
        CP_ASYNC16(base + A_BYTES + sw,
                   (const char*)g_Wb + ((size_t)(n0 + r) * DIM + k0 + c * 8) * 2);
    }
    CP_COMMIT();
}

// ---------------- fused HMMA GEMM + softmax-stats -----------------------------
// grid (VOCAB/BN=125, NROWS/BM=32), 256 threads, warp grid 2(M) x 4(N),
// warp tile 64x64, fp16 acc, 2-stage ring, 2 CTAs/SM (tail overlap).
__global__ void __launch_bounds__(256, 2) ce_kernel(const void* yraw) {
    extern __shared__ char smem[];
    __shared__ double s_red[8];
    uint32_t sbase = s2u(smem);

    const int tid = threadIdx.x, warp = tid >> 5, lane = tid & 31;
    const int n0 = blockIdx.x * BN, m0 = blockIdx.y * BM;
    const int wm = (warp >> 2) * 64, wn = (warp & 3) * 64;

    uint32_t acc[4][8][2];
    #pragma unroll
    for (int mi = 0; mi < 4; mi++)
        #pragma unroll
        for (int ni = 0; ni < 8; ni++) { acc[mi][ni][0] = 0u; acc[mi][ni][1] = 0u; }

    issue_stage(sbase, 0, 0, m0, n0, tid);
    issue_stage(sbase, 1, 1, m0, n0, tid);

    // precomputed ldmatrix lane addressing
    const int a_r = (lane & 15);            // + wm + 16*mi
    const int a_cbit = (lane >> 4);         // +2*ks
    const int b_r = (lane & 7) + ((lane >> 4) << 3);   // + wn + 16*np
    const int b_cbit = ((lane >> 3) & 1);   // +2*ks

    for (int kt = 0; kt < NKITER; kt++) {
        int s = kt & 1;
        CP_WAIT1();              // stage kt landed (kt+1 may still fly)
        __syncthreads();

        uint32_t abase = sbase + s * STAGE_BYTES;
        uint32_t bbase = abase + A_BYTES;
        #pragma unroll
        for (int ks = 0; ks < 4; ks++) {
            uint32_t af[4][4];
            #pragma unroll
            for (int mi = 0; mi < 4; mi++) {
                int r = wm + mi * 16 + a_r;
                int c = ks * 2 + a_cbit;
                ldsm4(af[mi][0], af[mi][1], af[mi][2], af[mi][3],
                      abase + r * 128 + ((c ^ (r & 7)) << 4));
            }
            uint32_t bf[8][2];
            #pragma unroll
            for (int np = 0; np < 4; np++) {
                int r = wn + np * 16 + b_r;
                int c = ks * 2 + b_cbit;
                uint32_t q0, q1, q2, q3;
                ldsm4(q0, q1, q2, q3, bbase + r * 128 + ((c ^ (r & 7)) << 4));
                bf[np * 2][0] = q0;     bf[np * 2][1] = q1;
                bf[np * 2 + 1][0] = q2; bf[np * 2 + 1][1] = q3;
            }
            #pragma unroll
            for (int mi = 0; mi < 4; mi++)
                #pragma unroll
                for (int ni = 0; ni < 8; ni++)
                    mma16816h(acc[mi][ni], af[mi], bf[ni]);
        }

        // refill the buffer we just consumed (all warps done reading: barrier)
        if (kt + 2 < NKITER) {
            __syncthreads();
            issue_stage(sbase, kt + 2, s, m0, n0, tid);
        }
    }

    // ---------------- epilogue from registers ----------------
    // acc[mi][ni][rr] packs halves {(r + 8rr, n), (r + 8rr, n+1)},
    //   r = wm+16mi+lane/4, n = wn+8ni+2*(lane&3)
    const int ymode = g_ymode;
    float sl = 0.0f;
    #pragma unroll
    for (int mi = 0; mi < 4; mi++) {
        #pragma unroll
        for (int rr = 0; rr < 2; rr++) {
            int row = m0 + wm + mi * 16 + rr * 8 + (lane >> 2);
            long long yv = ymode ? ((const long long*)yraw)[row]
                                 : (long long)((const int*)yraw)[row];
            int jt = (int)yv - (n0 + wn);   // target col within this warp's 64-span
            float se = 0.0f;
            #pragma unroll
            for (int ni = 0; ni < 8; ni++) {
                float2 v = __half22float2(*(const __half2*)&acc[mi][ni][rr]);
                se += __expf(v.x) + __expf(v.y);
                sl += v.x + v.y;
                int cb = ni * 8 + ((lane & 3) << 1);
                if (cb == jt)     g_tgt[row] = v.x;
                if (cb + 1 == jt) g_tgt[row] = v.y;
            }
            se += __shfl_xor_sync(0xffffffffu, se, 1);
            se += __shfl_xor_sync(0xffffffffu, se, 2);
            if ((lane & 3) == 0) atomicAdd(&g_rowS[row], se);
        }
    }
    #pragma unroll
    for (int o = 16; o > 0; o >>= 1) sl += __shfl_xor_sync(0xffffffffu, sl, o);
    if (lane == 0) s_red[warp] = (double)sl;
    __syncthreads();
    if (tid == 0) {
        double t = 0.0;
        #pragma unroll
        for (int i = 0; i < 8; i++) t += s_red[i];
        atomicAdd(&g_sumAll, t);
    }
}

// ---------------- finalize: parallel partials + last-block combine ------------
__global__ void finalize_kernel(float* out) {
    __shared__ double sa[256], sb[256];
    __shared__ int s_last;
    int t = threadIdx.x;
    double a = 0.0, b = 0.0;
    for (int n = blockIdx.x * 256 + t; n < NROWS; n += FIN_BLOCKS * 256) {
        a += (double)logf(g_rowS[n]);
        b += (double)g_tgt[n];
    }
    sa[t] = a; sb[t] = b;
    __syncthreads();
    for (int o = 128; o > 0; o >>= 1) {
        if (t < o) { sa[t] += sa[t + o]; sb[t] += sb[t + o]; }
        __syncthreads();
    }
    if (t == 0) {
        atomicAdd(&g_fa, sa[0]);
        atomicAdd(&g_fb, sb[0]);
        __threadfence();
        unsigned int prev = atomicAdd(&g_fdone, 1u);
        s_last = (prev == FIN_BLOCKS - 1u) ? 1 : 0;
    }
    __syncthreads();
    if (s_last && t == 0) {
        __threadfence();
        double loss = g_fa / (double)NROWS
                    - 0.9 * g_fb / (double)NROWS
                    - 0.1 * (g_sumAll / ((double)NROWS * (double)VOCAB));
        out[0] = (float)loss;
    }
}

// ---------------- launch ----------------
extern "C" void kernel_launch(void* const* d_in, const int* in_sizes, int n_in,
                              void* d_out, int out_size) {
    const float* x = (const float*)d_in[0];
    const float* W = (const float*)d_in[1];
    const void*  y = d_in[2];

    cudaFuncSetAttribute(ce_kernel, cudaFuncAttributeMaxDynamicSharedMemorySize, SMEM_BYTES);

    convert_kernel<<<2048, 256>>>(x, W, y);
    dim3 grid(VOCAB / BN, NROWS / BM);
    ce_kernel<<<grid, 256, SMEM_BYTES>>>(y);
    finalize_kernel<<<FIN_BLOCKS, 256>>>((float*)d_out);
}